// round 6
// baseline (speedup 1.0000x reference)
#include <cuda_runtime.h>

#define TPB        512
#define ROWS_TILE  128          // rows per row-tile
#define NSLICE     8            // j-slices per row-tile (split-K)
#define CHUNKS     8            // intra-CTA j-split (threads: 64 row-pairs x 8 chunks)
#define MAX_RT     128
#define MAX_BATCH  16384

__device__ float g_partial[NSLICE][MAX_BATCH * 3];
__device__ int   g_cnt[MAX_RT];

typedef unsigned long long u64t;

__device__ __forceinline__ u64t pk2(float a, float b) {
    u64t r;
    asm("mov.b64 %0, {%1, %2};" : "=l"(r)
        : "r"(__float_as_uint(a)), "r"(__float_as_uint(b)));
    return r;
}
__device__ __forceinline__ void upk2(u64t v, float& a, float& b) {
    unsigned int x, y;
    asm("mov.b64 {%0, %1}, %2;" : "=r"(x), "=r"(y) : "l"(v));
    a = __uint_as_float(x);
    b = __uint_as_float(y);
}
__device__ __forceinline__ u64t fma2(u64t a, u64t b, u64t c) {
    u64t d;
    asm("fma.rn.f32x2 %0, %1, %2, %3;" : "=l"(d) : "l"(a), "l"(b), "l"(c));
    return d;
}
__device__ __forceinline__ u64t add2(u64t a, u64t b) {
    u64t d;
    asm("add.rn.f32x2 %0, %1, %2;" : "=l"(d) : "l"(a), "l"(b));
    return d;
}

__global__ void __launch_bounds__(TPB, 1)
tps_main(const float* __restrict__ u,
         const float* __restrict__ cp,
         const float* __restrict__ w,
         const float* __restrict__ poly,
         float* __restrict__ out,
         int batch, int n) {
    // Static smem: replicated control points for f32x2 math.
    __shared__ ulonglong2 s_cA[512];  // { {-2cx,-2cx}, {-2cy,-2cy} }
    __shared__ ulonglong2 s_cB[512];  // { {-2cz,-2cz}, { c2 , c2 } }
    __shared__ float4     s_w [512];  // { w0, w1, w2, 0 }
    __shared__ float      s_red[(CHUNKS - 1) * 64 * 6];
    __shared__ int        s_flag;

    const int tid   = threadIdx.x;
    const int bid   = blockIdx.x;
    const int slice = bid & (NSLICE - 1);
    const int rt    = bid >> 3;          // row-tile index
    const int jlen  = n / NSLICE;        // 512
    const int jc    = jlen / CHUNKS;     // 64
    const int j0g   = slice * jlen;

    // ---- stage + transform this slice's control points / weights ----
    for (int jj = tid; jj < jlen; jj += TPB) {
        int j = j0g + jj;
        float cx = cp[3 * j + 0];
        float cy = cp[3 * j + 1];
        float cz = cp[3 * j + 2];
        float c2 = fmaf(cx, cx, fmaf(cy, cy, cz * cz));
        float nx = -2.0f * cx, ny = -2.0f * cy, nz = -2.0f * cz;
        s_cA[jj] = make_ulonglong2(pk2(nx, nx), pk2(ny, ny));
        s_cB[jj] = make_ulonglong2(pk2(nz, nz), pk2(c2, c2));
        s_w[jj]  = make_float4(w[3 * j + 0], w[3 * j + 1], w[3 * j + 2], 0.0f);
    }
    __syncthreads();

    // ---- thread layout: 64 row-pairs x 8 j-chunks ----
    const int p  = tid & 63;             // row-pair slot
    const int c  = tid >> 6;             // j-chunk 0..7
    const int r0 = rt * ROWS_TILE + 2 * p;
    const int r1 = r0 + 1;

    float ux0 = u[3 * r0 + 0], uy0 = u[3 * r0 + 1], uz0 = u[3 * r0 + 2];
    float ux1 = u[3 * r1 + 0], uy1 = u[3 * r1 + 1], uz1 = u[3 * r1 + 2];
    float u20 = fmaf(ux0, ux0, fmaf(uy0, uy0, uz0 * uz0));
    float u21 = fmaf(ux1, ux1, fmaf(uy1, uy1, uz1 * uz1));

    const u64t UX  = pk2(ux0, ux1);
    const u64t UY  = pk2(uy0, uy1);
    const u64t UZ  = pk2(uz0, uz1);
    const u64t U22 = pk2(u20, u21);

    float a00 = 0.f, a01 = 0.f, a02 = 0.f;
    float a10 = 0.f, a11 = 0.f, a12 = 0.f;

    const int jb = c * jc, je = jb + jc;
    #pragma unroll 8
    for (int jj = jb; jj < je; ++jj) {
        ulonglong2 A  = s_cA[jj];
        ulonglong2 B  = s_cB[jj];
        float4     wj = s_w[jj];
        // sq2 = |u|^2 + |c|^2 - 2 u.c  for two rows at once (expanded-form cdist)
        u64t sq2 = fma2(A.x, UX, fma2(A.y, UY, fma2(B.x, UZ, add2(B.y, U22))));
        float s0, s1;
        upk2(sq2, s0, s1);
        s0 = fmaxf(s0, 1e-20f);          // absorbs r<EPS -> 0 branch (k ~ -6.6e-9)
        s1 = fmaxf(s1, 1e-20f);
        float q0, l0, q1, l1;
        asm("sqrt.approx.f32 %0, %1;" : "=f"(q0) : "f"(s0));
        asm("lg2.approx.f32 %0, %1;"  : "=f"(l0) : "f"(s0));
        asm("sqrt.approx.f32 %0, %1;" : "=f"(q1) : "f"(s1));
        asm("lg2.approx.f32 %0, %1;"  : "=f"(l1) : "f"(s1));
        float k0 = q0 * l0;              // true k = 0.5*ln2 * sqrt(sq)*lg2(sq)
        float k1 = q1 * l1;
        a00 = fmaf(k0, wj.x, a00); a01 = fmaf(k0, wj.y, a01); a02 = fmaf(k0, wj.z, a02);
        a10 = fmaf(k1, wj.x, a10); a11 = fmaf(k1, wj.y, a11); a12 = fmaf(k1, wj.z, a12);
    }

    // ---- intra-CTA reduction over the 8 j-chunks ----
    if (c > 0) {
        float* dst = &s_red[((c - 1) * 64 + p) * 6];
        dst[0] = a00; dst[1] = a01; dst[2] = a02;
        dst[3] = a10; dst[4] = a11; dst[5] = a12;
    }
    __syncthreads();

    if (c == 0) {
        #pragma unroll
        for (int cc = 0; cc < CHUNKS - 1; ++cc) {
            float* src = &s_red[(cc * 64 + p) * 6];
            a00 += src[0]; a01 += src[1]; a02 += src[2];
            a10 += src[3]; a11 += src[4]; a12 += src[5];
        }
        float* gp = g_partial[slice];
        gp[3 * r0 + 0] = a00; gp[3 * r0 + 1] = a01; gp[3 * r0 + 2] = a02;
        gp[3 * r1 + 0] = a10; gp[3 * r1 + 1] = a11; gp[3 * r1 + 2] = a12;
    }
    __threadfence();
    __syncthreads();

    // ---- last CTA of this row-tile does the fixed-order fixup (deterministic) ----
    if (tid == 0) {
        int v = atomicAdd(&g_cnt[rt], 1);
        s_flag = (v == NSLICE - 1);
    }
    __syncthreads();

    if (s_flag) {
        __threadfence();
        const float C = 0.34657359027997264f;    // 0.5 * ln(2)
        for (int idx = tid; idx < ROWS_TILE * 3; idx += TPB) {
            int rloc = idx / 3, comp = idx - 3 * rloc;
            int row  = rt * ROWS_TILE + rloc;
            float sum = 0.0f;
            #pragma unroll
            for (int ss = 0; ss < NSLICE; ++ss)
                sum += g_partial[ss][3 * row + comp];
            float vx = u[3 * row + 0], vy = u[3 * row + 1], vz = u[3 * row + 2];
            float pp = poly[comp]
                     + fmaf(vx, poly[3 + comp],
                       fmaf(vy, poly[6 + comp], vz * poly[9 + comp]));
            out[3 * row + comp] = fmaf(C, sum, pp);
        }
        if (tid == 0) g_cnt[rt] = 0;   // self-reset for graph replay
    }
}

extern "C" void kernel_launch(void* const* d_in, const int* in_sizes, int n_in,
                              void* d_out, int out_size) {
    const float* u    = (const float*)d_in[0];
    const float* cp   = (const float*)d_in[1];
    const float* w    = (const float*)d_in[2];
    const float* poly = (const float*)d_in[3];
    float* out = (float*)d_out;

    int batch = in_sizes[0] / 3;
    int n     = in_sizes[1] / 3;

    int nrt    = batch / ROWS_TILE;        // 128
    int blocks = nrt * NSLICE;             // 1024
    tps_main<<<blocks, TPB>>>(u, cp, w, poly, out, batch, n);
}